// round 12
// baseline (speedup 1.0000x reference)
#include <cuda_runtime.h>

#define Nn    4096
#define Bb    4
#define Kk    8
#define BN    (Bb * Nn)         // 16384 points per cloud
#define TPB   512               // 256 queries/block, 2 threads per query (L/R)
#define PPB   256
#define CB    64
#define CTPB  256
#define EPSF  1e-12f
#define BIGF  3.4e38f

// ---- device scratch ----
__device__ float4 g_sorted[2 * BN];         // [cloud*Bb+b][slot] (x,y,z,|p|^2), x-ascending
__device__ int    g_oid   [2 * BN];         // original index per sorted slot
__device__ float  g_dens  [2 * BN];
__device__ float  g_cov   [2 * 6 * BN];
__device__ float  g_nv    [2 * Kk * 3 * BN];
__device__ float  g_part  [3 * CB];

// ============ Kernel A: per-(batch,cloud) bitonic sort by x ============
__global__ void __launch_bounds__(1024)
sort_kernel(const float* __restrict__ pred, const float* __restrict__ target) {
    __shared__ float key[Nn];
    __shared__ int   idx[Nn];
    const int tid = threadIdx.x;
    const int b   = blockIdx.x;
    const int c   = blockIdx.y;
    const float* src = (c == 0 ? pred : target) + (size_t)b * Nn * 3;

    for (int t = tid; t < Nn; t += 1024) { key[t] = src[3*t]; idx[t] = t; }
    __syncthreads();

    for (int kk = 2; kk <= Nn; kk <<= 1) {
        for (int jj = kk >> 1; jj > 0; jj >>= 1) {
#pragma unroll 4
            for (int t = tid; t < Nn; t += 1024) {
                int ixj = t ^ jj;
                if (ixj > t) {
                    bool up = ((t & kk) == 0);
                    float a = key[t], d = key[ixj];
                    if ((a > d) == up) {
                        key[t] = d; key[ixj] = a;
                        int ia = idx[t]; idx[t] = idx[ixj]; idx[ixj] = ia;
                    }
                }
            }
            __syncthreads();
        }
    }

    const int cb = (c * Bb + b) * Nn;
    for (int s = tid; s < Nn; s += 1024) {
        int oi = idx[s];
        float x = src[3*oi+0], y = src[3*oi+1], z = src[3*oi+2];
        g_sorted[cb + s] = make_float4(x, y, z, fmaf(x, x, fmaf(y, y, z*z)));
        g_oid[cb + s] = oi;
    }
}

// Parallel-rank insert of (v, j) into ascending 8-list. No-op safe for v >= bd[7].
__device__ __forceinline__ void insert8(float bd[8], int bi[8], float v, int j) {
    bool c[8];
#pragma unroll
    for (int t = 0; t < 8; t++) c[t] = v < bd[t];
#pragma unroll
    for (int t = 7; t >= 1; t--) {
        bd[t] = c[t] ? (c[t-1] ? bd[t-1] : v) : bd[t];
        bi[t] = c[t] ? (c[t-1] ? bi[t-1] : j) : bi[t];
    }
    bd[0] = c[0] ? v : bd[0];
    bi[0] = c[0] ? j : bi[0];
}

// Merge two sorted 8-lists (ascending); result in (bd,bi).
__device__ __forceinline__ void merge8(float bd[8], int bi[8],
                                       const float* __restrict__ ld,
                                       const int*   __restrict__ li) {
    float ed[8]; int ei[8];
#pragma unroll
    for (int t = 0; t < 8; t++) { ed[t] = ld[t]; ei[t] = li[t]; }
    float od[8]; int oi[8];
#pragma unroll
    for (int r = 0; r < 8; r++) {
        bool ta = bd[0] <= ed[0];
        od[r] = ta ? bd[0] : ed[0];
        oi[r] = ta ? bi[0] : ei[0];
#pragma unroll
        for (int t = 0; t < 7; t++) {
            bd[t] = ta ? bd[t+1] : bd[t];
            bi[t] = ta ? bi[t+1] : bi[t];
            ed[t] = ta ? ed[t]   : ed[t+1];
            ei[t] = ta ? ei[t]   : ei[t+1];
        }
        bd[7] = ta ? BIGF : bd[7];
        ed[7] = ta ? ed[7] : BIGF;
    }
#pragma unroll
    for (int t = 0; t < 8; t++) { bd[t] = od[t]; bi[t] = oi[t]; }
}

// ============ Kernel B: pruned outward kNN scan ============
// Block: 256 consecutive sorted queries of one (batch, cloud);
// threads 0-255 scan right (slots s+1, s+2, ...), 256-511 scan left.
__global__ void __launch_bounds__(TPB)
knn_scan_kernel() {
    extern __shared__ char smem_raw[];
    float4* sc   = (float4*)smem_raw;                        // [Nn] sorted cloud
    float*  lstd = (float*)(smem_raw + Nn * sizeof(float4)); // [PPB*8]
    int*    lsti = (int*)(lstd + PPB * 8);                   // [PPB*8]

    const int tid  = threadIdx.x;
    const int b    = blockIdx.y;
    const int c    = blockIdx.z;
    const int pl   = tid & (PPB - 1);
    const int half = tid >> 8;               // 0 = right scan, 1 = left scan
    const int cb   = (c * Bb + b) * Nn;

    for (int p = tid; p < Nn; p += TPB) sc[p] = g_sorted[cb + p];
    __syncthreads();

    const int s = blockIdx.x * PPB + pl;     // sorted slot of this query
    const float4 Pi = sc[s];

    float bd[8]; int bi[8];
#pragma unroll
    for (int t = 0; t < 8; t++) { bd[t] = BIGF; bi[t] = s; }

    const int step = half ? -1 : 1;
    int  j      = s + step;
    bool active = (j >= 0) && (j < Nn);
    float thr   = BIGF;                      // == bd[7]

    while (__any_sync(0xffffffffu, active)) {
        int jc = active ? j : s;             // safe smem read when done
        float4 q = sc[jc];
        float dx = q.x - Pi.x;
        float dxsq = dx * dx;
        float dy = q.y - Pi.y, dz = q.z - Pi.z;
        float d2 = fmaf(dz, dz, fmaf(dy, dy, dxsq));
        active = active && (dxsq < thr);     // exact pruning: d2 >= dxsq
        float v = active ? d2 : BIGF;
        if (__any_sync(0xffffffffu, v < thr)) {
            insert8(bd, bi, v, jc);
            thr = bd[7];
        }
        j += step;
        active = active && (j >= 0) && (j < Nn);
    }

    // left-scanners publish their sorted lists (stride-8, conflict-free enough)
    if (half == 1) {
        float* dd = lstd + pl * 8;
        int*   ii = lsti + pl * 8;
#pragma unroll
        for (int t = 0; t < 8; t++) { dd[t] = bd[t]; ii[t] = bi[t]; }
    }
    __syncthreads();
    if (half == 1) return;

    merge8(bd, bi, lstd + pl * 8, lsti + pl * 8);

    // ---- epilogue: density, covariance, normalized neighbor vectors ----
    const int base = b * Nn + g_oid[cb + s];   // scatter to original index
    float dens = 0.f;
    float cxx = 0.f, cyy = 0.f, czz = 0.f, cxy = 0.f, cxz = 0.f, cyz = 0.f;
#pragma unroll
    for (int k = 0; k < Kk; k++) {
        dens += sqrtf(fmaxf(bd[k], EPSF));
        float4 q = sc[bi[k]];
        float vx = q.x - Pi.x, vy = q.y - Pi.y, vz = q.z - Pi.z;
        cxx = fmaf(vx, vx, cxx); cyy = fmaf(vy, vy, cyy); czz = fmaf(vz, vz, czz);
        cxy = fmaf(vx, vy, cxy); cxz = fmaf(vx, vz, cxz); cyz = fmaf(vy, vz, cyz);
        float nrm = sqrtf(fmaf(vx, vx, fmaf(vy, vy, vz * vz)));
        float inv = 1.0f / fmaxf(nrm, EPSF);
        g_nv[((c*Kk + k)*3 + 0)*BN + base] = vx * inv;
        g_nv[((c*Kk + k)*3 + 1)*BN + base] = vy * inv;
        g_nv[((c*Kk + k)*3 + 2)*BN + base] = vz * inv;
    }
    g_dens[c*BN + base]        = dens * 0.125f;
    g_cov[(c*6 + 0)*BN + base] = cxx * 0.125f;
    g_cov[(c*6 + 1)*BN + base] = cyy * 0.125f;
    g_cov[(c*6 + 2)*BN + base] = czz * 0.125f;
    g_cov[(c*6 + 3)*BN + base] = cxy * 0.125f;
    g_cov[(c*6 + 4)*BN + base] = cxz * 0.125f;
    g_cov[(c*6 + 5)*BN + base] = cyz * 0.125f;
}

// ============ combine + finalize (unchanged) ============
__global__ void __launch_bounds__(CTPB)
combine_kernel() {
    const int tid = threadIdx.x;
    const int idx = blockIdx.x * CTPB + tid;

    float dd = g_dens[idx] - g_dens[BN + idx];
    float c_den = dd * dd;

    float fro = 0.f;
#pragma unroll
    for (int s = 0; s < 6; s++) {
        float e = g_cov[s*BN + idx] - g_cov[(6 + s)*BN + idx];
        float w = (s < 3) ? 1.0f : 2.0f;
        fro = fmaf(w * e, e, fro);
    }
    float c_cur = sqrtf(fro);

    float dsum = 0.f;
#pragma unroll
    for (int e = 0; e < Kk * 3; e++)
        dsum = fmaf(g_nv[e*BN + idx], g_nv[(Kk*3 + e)*BN + idx], dsum);

    __shared__ float r[3 * CTPB];
    r[tid]          = c_den;
    r[CTPB + tid]   = dsum;
    r[2*CTPB + tid] = c_cur;
    __syncthreads();
#pragma unroll
    for (int s = CTPB / 2; s > 0; s >>= 1) {
        if (tid < s) {
            r[tid]          += r[tid + s];
            r[CTPB + tid]   += r[CTPB + tid + s];
            r[2*CTPB + tid] += r[2*CTPB + tid + s];
        }
        __syncthreads();
    }
    if (tid == 0) {
        g_part[blockIdx.x]        = r[0];
        g_part[CB + blockIdx.x]   = r[CTPB];
        g_part[2*CB + blockIdx.x] = r[2*CTPB];
    }
}

__global__ void __launch_bounds__(CB) finalize_kernel(float* __restrict__ out) {
    __shared__ float r[3 * CB];
    int tid = threadIdx.x;
    r[tid]        = g_part[tid];
    r[CB + tid]   = g_part[CB + tid];
    r[2*CB + tid] = g_part[2*CB + tid];
    __syncthreads();
#pragma unroll
    for (int s = CB / 2; s > 0; s >>= 1) {
        if (tid < s) {
            r[tid]        += r[tid + s];
            r[CB + tid]   += r[CB + tid + s];
            r[2*CB + tid] += r[2*CB + tid + s];
        }
        __syncthreads();
    }
    if (tid == 0) {
        const float invBN = 1.0f / (float)BN;
        float density_loss   = r[0] * invBN;
        float direction_loss = 1.0f - r[CB] * (invBN / (float)Kk);
        float curvature_loss = r[2*CB] * invBN;
        out[0] = density_loss + 0.5f * direction_loss + 0.5f * curvature_loss;
    }
}

extern "C" void kernel_launch(void* const* d_in, const int* in_sizes, int n_in,
                              void* d_out, int out_size) {
    (void)in_sizes; (void)n_in; (void)out_size;
    const float* pred   = (const float*)d_in[0];
    const float* target = (const float*)d_in[1];

    size_t smem_bytes = (size_t)Nn * sizeof(float4)
                      + (size_t)PPB * 8 * (sizeof(float) + sizeof(int)); // 80 KB
    cudaFuncSetAttribute(knn_scan_kernel,
                         cudaFuncAttributeMaxDynamicSharedMemorySize,
                         (int)smem_bytes);

    sort_kernel<<<dim3(Bb, 2), 1024>>>(pred, target);
    dim3 grid(Nn / PPB, Bb, 2);                 // 128 blocks, 512 threads each
    knn_scan_kernel<<<grid, TPB, smem_bytes>>>();
    combine_kernel<<<CB, CTPB>>>();
    finalize_kernel<<<1, CB>>>((float*)d_out);
}

// round 13
// speedup vs baseline: 1.9686x; 1.9686x over previous
#include <cuda_runtime.h>

#define Nn    4096
#define Bb    4
#define Kk    8
#define BN    (Bb * Nn)         // 16384 points per cloud
#define TPB   512               // 256 points/block, 2 threads per point
#define PPB   256               // points per block
#define HALF  (Nn / 2)          // candidates per thread
#define CB    64
#define CTPB  256
#define EPSF  1e-12f
#define KINIT 0x7F7FF000u       // huge-float key; |0xFFF -> FLT_MAX threshold

// ---- device scratch (SoA, coalesced) ----
__device__ float g_dens[2 * BN];
__device__ float g_cov [2 * 6 * BN];
__device__ float g_nv  [2 * Kk * 3 * BN];
__device__ float g_part[3 * CB];

// Ladder-insert key v into ascending 9-list of u32 keys (branch-free, no-op
// safe when v exceeds kd[8]).
__device__ __forceinline__ void ladder9(unsigned kd[9], unsigned v) {
#pragma unroll
    for (int t = 0; t < 9; t++) {
        unsigned lo = umin(kd[t], v);
        v = umax(kd[t], v);
        kd[t] = lo;
    }
}

// Scan HALF candidates from j0; keep 9 smallest (d2, idx) packed keys.
// key = (bits(max(d2,0)) & ~0xFFF) | j  -> unsigned order == (d2_trunc, j).
__device__ __forceinline__ void scan9(const float4* __restrict__ s, int j0,
                                      float px, float py, float pz, float sq,
                                      unsigned kd[9]) {
#pragma unroll
    for (int t = 0; t < 9; t++) kd[t] = KINIT;
    const float m2x = -2.0f * px, m2y = -2.0f * py, m2z = -2.0f * pz;
    float thrf = __uint_as_float(KINIT | 0xFFFu);   // conservative threshold
    const int jend = j0 + HALF;
#pragma unroll 4
    for (int j = j0; j < jend; j++) {
        float4 q = s[j];
        float base = sq + q.w;
        float d2 = fmaf(m2x, q.x, fmaf(m2y, q.y, fmaf(m2z, q.z, base)));
        if (__any_sync(0xffffffffu, d2 <= thrf)) {
            float vc = fmaxf(d2, 0.0f);
            unsigned v = (__float_as_uint(vc) & 0xFFFFF000u) | (unsigned)j;
            ladder9(kd, v);
            thrf = __uint_as_float(kd[8] | 0xFFFu);
        }
    }
}

// Block: 256 points of one (batch, cloud), 2 threads/point (candidate halves).
__global__ void __launch_bounds__(TPB)
knn_scan_kernel(const float* __restrict__ pred, const float* __restrict__ target) {
    extern __shared__ char smem_raw[];
    float4*   sc   = (float4*)smem_raw;                          // [Nn] cloud
    unsigned* lstk = (unsigned*)(smem_raw + Nn * sizeof(float4)); // [PPB*9]

    const int tid  = threadIdx.x;
    const int b    = blockIdx.y;
    const int c    = blockIdx.z;             // 0 = pred, 1 = target
    const int pl   = tid & (PPB - 1);        // local point
    const int half = tid >> 8;               // candidate half 0/1

    const float* src = (c == 0 ? pred : target) + (size_t)b * Nn * 3;
    for (int p = tid; p < Nn; p += TPB) {
        float x = src[3*p+0], y = src[3*p+1], z = src[3*p+2];
        sc[p] = make_float4(x, y, z, fmaf(x, x, fmaf(y, y, z*z)));
    }
    __syncthreads();

    const int i  = blockIdx.x * PPB + pl;
    const float4 Pi = sc[i];

    unsigned kd[9];
    scan9(sc, half * HALF, Pi.x, Pi.y, Pi.z, Pi.w, kd);

    // half-B publishes its sorted key list (stride-9 -> conflict-free)
    if (half == 1) {
        unsigned* dd = lstk + pl * 9;
#pragma unroll
        for (int t = 0; t < 9; t++) dd[t] = kd[t];
    }
    __syncthreads();
    if (half == 1) return;

    // merge: ladder-insert B's 9 keys into A's list (keys unique -> exact)
    {
        const unsigned* dd = lstk + pl * 9;
#pragma unroll
        for (int m = 0; m < 9; m++) ladder9(kd, dd[m]);
    }

    // ---- epilogue: slots 1..8 are the 8 neighbors (slot 0 = self) ----
    const int base = b * Nn + i;
    float dens = 0.f;
    float cxx = 0.f, cyy = 0.f, czz = 0.f, cxy = 0.f, cxz = 0.f, cyz = 0.f;
#pragma unroll
    for (int k = 0; k < Kk; k++) {
        int j = (int)(kd[k+1] & 0xFFFu);
        float4 q = sc[j];
        float vx = q.x - Pi.x, vy = q.y - Pi.y, vz = q.z - Pi.z;
        cxx = fmaf(vx, vx, cxx); cyy = fmaf(vy, vy, cyy); czz = fmaf(vz, vz, czz);
        cxy = fmaf(vx, vy, cxy); cxz = fmaf(vx, vz, cxz); cyz = fmaf(vy, vz, cyz);
        float nrm = sqrtf(fmaf(vx, vx, fmaf(vy, vy, vz * vz)));
        dens += fmaxf(nrm, 1e-6f);           // sqrt(max(d2,1e-12))
        float inv = 1.0f / fmaxf(nrm, EPSF);
        g_nv[((c*Kk + k)*3 + 0)*BN + base] = vx * inv;
        g_nv[((c*Kk + k)*3 + 1)*BN + base] = vy * inv;
        g_nv[((c*Kk + k)*3 + 2)*BN + base] = vz * inv;
    }
    g_dens[c*BN + base]        = dens * 0.125f;
    g_cov[(c*6 + 0)*BN + base] = cxx * 0.125f;
    g_cov[(c*6 + 1)*BN + base] = cyy * 0.125f;
    g_cov[(c*6 + 2)*BN + base] = czz * 0.125f;
    g_cov[(c*6 + 3)*BN + base] = cxy * 0.125f;
    g_cov[(c*6 + 4)*BN + base] = cxz * 0.125f;
    g_cov[(c*6 + 5)*BN + base] = cyz * 0.125f;
}

// Pair pred/target stats per point, partial-reduce per block.
__global__ void __launch_bounds__(CTPB)
combine_kernel() {
    const int tid = threadIdx.x;
    const int idx = blockIdx.x * CTPB + tid;

    float dd = g_dens[idx] - g_dens[BN + idx];
    float c_den = dd * dd;

    float fro = 0.f;
#pragma unroll
    for (int s = 0; s < 6; s++) {
        float e = g_cov[s*BN + idx] - g_cov[(6 + s)*BN + idx];
        float w = (s < 3) ? 1.0f : 2.0f;
        fro = fmaf(w * e, e, fro);
    }
    float c_cur = sqrtf(fro);

    float dsum = 0.f;
#pragma unroll
    for (int e = 0; e < Kk * 3; e++)
        dsum = fmaf(g_nv[e*BN + idx], g_nv[(Kk*3 + e)*BN + idx], dsum);

    __shared__ float r[3 * CTPB];
    r[tid]          = c_den;
    r[CTPB + tid]   = dsum;
    r[2*CTPB + tid] = c_cur;
    __syncthreads();
#pragma unroll
    for (int s = CTPB / 2; s > 0; s >>= 1) {
        if (tid < s) {
            r[tid]          += r[tid + s];
            r[CTPB + tid]   += r[CTPB + tid + s];
            r[2*CTPB + tid] += r[2*CTPB + tid + s];
        }
        __syncthreads();
    }
    if (tid == 0) {
        g_part[blockIdx.x]        = r[0];
        g_part[CB + blockIdx.x]   = r[CTPB];
        g_part[2*CB + blockIdx.x] = r[2*CTPB];
    }
}

__global__ void __launch_bounds__(CB) finalize_kernel(float* __restrict__ out) {
    __shared__ float r[3 * CB];
    int tid = threadIdx.x;
    r[tid]        = g_part[tid];
    r[CB + tid]   = g_part[CB + tid];
    r[2*CB + tid] = g_part[2*CB + tid];
    __syncthreads();
#pragma unroll
    for (int s = CB / 2; s > 0; s >>= 1) {
        if (tid < s) {
            r[tid]        += r[tid + s];
            r[CB + tid]   += r[CB + tid + s];
            r[2*CB + tid] += r[2*CB + tid + s];
        }
        __syncthreads();
    }
    if (tid == 0) {
        const float invBN = 1.0f / (float)BN;
        float density_loss   = r[0] * invBN;
        float direction_loss = 1.0f - r[CB] * (invBN / (float)Kk);
        float curvature_loss = r[2*CB] * invBN;
        out[0] = density_loss + 0.5f * direction_loss + 0.5f * curvature_loss;
    }
}

extern "C" void kernel_launch(void* const* d_in, const int* in_sizes, int n_in,
                              void* d_out, int out_size) {
    (void)in_sizes; (void)n_in; (void)out_size;
    const float* pred   = (const float*)d_in[0];
    const float* target = (const float*)d_in[1];

    size_t smem_bytes = (size_t)Nn * sizeof(float4)
                      + (size_t)PPB * 9 * sizeof(unsigned);   // ~73 KB
    cudaFuncSetAttribute(knn_scan_kernel,
                         cudaFuncAttributeMaxDynamicSharedMemorySize,
                         (int)smem_bytes);

    dim3 grid(Nn / PPB, Bb, 2);                 // 128 blocks, 512 threads each
    knn_scan_kernel<<<grid, TPB, smem_bytes>>>(pred, target);
    combine_kernel<<<CB, CTPB>>>();
    finalize_kernel<<<1, CB>>>((float*)d_out);
}